// round 1
// baseline (speedup 1.0000x reference)
#include <cuda_runtime.h>
#include <cuda_bf16.h>

// Problem constants (fixed by the dataset)
#define N_NODES 50000
#define E_EDGES 1000000
#define DIM     64
#define G_GRAPHS 512
#define O_DIM   16

// Scratch (allocation-free rule: __device__ globals)
__device__ float g_agg [N_NODES * DIM];   // 12.8 MB  (reused for both layers)
__device__ float g_h1  [N_NODES * DIM];   // 12.8 MB
__device__ float g_h2  [N_NODES * DIM];   // 12.8 MB
__device__ float g_pool[G_GRAPHS * DIM];  // 128 KB

// ---------------------------------------------------------------------------
// zero a float buffer (float4 grid-stride)
// ---------------------------------------------------------------------------
__global__ void zero_kernel(float4* __restrict__ p, int n4) {
    int i = blockIdx.x * blockDim.x + threadIdx.x;
    int stride = gridDim.x * blockDim.x;
    float4 z = make_float4(0.f, 0.f, 0.f, 0.f);
    for (; i < n4; i += stride) p[i] = z;
}

// ---------------------------------------------------------------------------
// scatter-add:  agg[dst] += feat[src]   (64 floats per edge)
// One edge handled by 16 threads; each thread moves one float4 and issues a
// vectorized L2 reduction (red.global.add.v4.f32, sm_90+).
// ---------------------------------------------------------------------------
__global__ void scatter_add_kernel(const float* __restrict__ feat,
                                   const int*   __restrict__ src,
                                   const int*   __restrict__ dst,
                                   float*       __restrict__ agg) {
    long long t = (long long)blockIdx.x * blockDim.x + threadIdx.x;
    int e = (int)(t >> 4);
    int l = (int)(t & 15);
    if (e >= E_EDGES) return;
    int s = __ldg(&src[e]);
    int d = __ldg(&dst[e]);
    float4 v = __ldg(&((const float4*)feat)[s * 16 + l]);
    float* p = &agg[d * 64 + l * 4];
    asm volatile("red.global.add.v4.f32 [%0], {%1,%2,%3,%4};"
                 :: "l"(p), "f"(v.x), "f"(v.y), "f"(v.z), "f"(v.w)
                 : "memory");
}

// ---------------------------------------------------------------------------
// fused SAGE GEMM:  out = relu( agg @ Wl + x @ Wr + b )
// Both 64x64 weight matrices live fully in smem. Block handles 32 rows with
// 256 threads: thread = (row 0..31, colgroup 0..7) -> 8 output columns.
// ---------------------------------------------------------------------------
__global__ __launch_bounds__(256) void sage_gemm_kernel(
        const float* __restrict__ agg, const float* __restrict__ xin,
        const float* __restrict__ Wl,  const float* __restrict__ Wr,
        const float* __restrict__ b,   float* __restrict__ out, int n) {
    __shared__ float sWl[64][64];
    __shared__ float sWr[64][64];
    __shared__ float sA [32][68];   // pad 68: rows hit distinct banks
    __shared__ float sX [32][68];
    __shared__ float sB [64];

    int tid = threadIdx.x;

    // weights: 1024 float4 each
    for (int i = tid; i < 1024; i += 256) {
        ((float4*)sWl)[i] = __ldg(&((const float4*)Wl)[i]);
        ((float4*)sWr)[i] = __ldg(&((const float4*)Wr)[i]);
    }
    if (tid < 64) sB[tid] = __ldg(&b[tid]);

    int row0 = blockIdx.x * 32;
    // tiles: 32 rows x 16 float4
    for (int i = tid; i < 512; i += 256) {
        int r  = i >> 4;       // 0..31
        int c4 = i & 15;       // 0..15
        int gr = row0 + r;
        float4 va = make_float4(0.f, 0.f, 0.f, 0.f);
        float4 vx = va;
        if (gr < n) {
            va = __ldg(&((const float4*)agg)[gr * 16 + c4]);
            vx = __ldg(&((const float4*)xin)[gr * 16 + c4]);
        }
        ((float4*)&sA[r][0])[c4] = va;
        ((float4*)&sX[r][0])[c4] = vx;
    }
    __syncthreads();

    int row = tid >> 3;           // 0..31
    int cg  = (tid & 7) * 8;      // column base 0,8,...,56

    float acc[8];
    #pragma unroll
    for (int j = 0; j < 8; j++) acc[j] = sB[cg + j];

    #pragma unroll
    for (int k = 0; k < 64; k++) {
        float a = sA[row][k];
        float h = sX[row][k];
        float4 wl0 = *(const float4*)&sWl[k][cg];
        float4 wl1 = *(const float4*)&sWl[k][cg + 4];
        float4 wr0 = *(const float4*)&sWr[k][cg];
        float4 wr1 = *(const float4*)&sWr[k][cg + 4];
        acc[0] += a * wl0.x + h * wr0.x;
        acc[1] += a * wl0.y + h * wr0.y;
        acc[2] += a * wl0.z + h * wr0.z;
        acc[3] += a * wl0.w + h * wr0.w;
        acc[4] += a * wl1.x + h * wr1.x;
        acc[5] += a * wl1.y + h * wr1.y;
        acc[6] += a * wl1.z + h * wr1.z;
        acc[7] += a * wl1.w + h * wr1.w;
    }

    int gr = row0 + row;
    if (gr < n) {
        float4 o0, o1;
        o0.x = fmaxf(acc[0], 0.f); o0.y = fmaxf(acc[1], 0.f);
        o0.z = fmaxf(acc[2], 0.f); o0.w = fmaxf(acc[3], 0.f);
        o1.x = fmaxf(acc[4], 0.f); o1.y = fmaxf(acc[5], 0.f);
        o1.z = fmaxf(acc[6], 0.f); o1.w = fmaxf(acc[7], 0.f);
        float4* op = (float4*)&out[gr * 64 + cg];
        op[0] = o0;
        op[1] = o1;
    }
}

// ---------------------------------------------------------------------------
// global add pool:  pool[batch[n]] += h2[n]
// ---------------------------------------------------------------------------
__global__ void pool_kernel(const float* __restrict__ h2,
                            const int*   __restrict__ batch,
                            float*       __restrict__ pool) {
    long long t = (long long)blockIdx.x * blockDim.x + threadIdx.x;
    int node = (int)(t >> 4);
    int l    = (int)(t & 15);
    if (node >= N_NODES) return;
    int bg = __ldg(&batch[node]);
    float4 v = __ldg(&((const float4*)h2)[node * 16 + l]);
    float* p = &pool[bg * 64 + l * 4];
    asm volatile("red.global.add.v4.f32 [%0], {%1,%2,%3,%4};"
                 :: "l"(p), "f"(v.x), "f"(v.y), "f"(v.z), "f"(v.w)
                 : "memory");
}

// ---------------------------------------------------------------------------
// head:  out = pool @ Wo + bo     [512,64] @ [64,16] -> [512,16]
// ---------------------------------------------------------------------------
__global__ void head_kernel(const float* __restrict__ pool,
                            const float* __restrict__ Wo,
                            const float* __restrict__ bo,
                            float*       __restrict__ out) {
    __shared__ float sW[64 * 16];
    __shared__ float sb[16];
    int tid = threadIdx.x;
    for (int i = tid; i < 64 * 16; i += 256) sW[i] = __ldg(&Wo[i]);
    if (tid < 16) sb[tid] = __ldg(&bo[tid]);
    __syncthreads();

    int t = blockIdx.x * blockDim.x + tid;
    if (t >= G_GRAPHS * O_DIM) return;
    int row = t >> 4;        // graph
    int col = t & 15;        // output dim
    float acc = sb[col];
    const float* pr = &pool[row * 64];
    #pragma unroll
    for (int k = 0; k < 64; k++) acc += pr[k] * sW[k * 16 + col];
    out[row * O_DIM + col] = acc;
}

// ---------------------------------------------------------------------------
// launch
// ---------------------------------------------------------------------------
extern "C" void kernel_launch(void* const* d_in, const int* in_sizes, int n_in,
                              void* d_out, int out_size) {
    const float* x   = (const float*)d_in[0];
    const int*   ei  = (const int*)  d_in[1];   // [2, E]: src row then dst row
    const int*   bat = (const int*)  d_in[2];
    const float* Wl1 = (const float*)d_in[3];
    const float* Wr1 = (const float*)d_in[4];
    const float* b1  = (const float*)d_in[5];
    const float* Wl2 = (const float*)d_in[6];
    const float* Wr2 = (const float*)d_in[7];
    const float* b2  = (const float*)d_in[8];
    const float* Wo  = (const float*)d_in[9];
    const float* bo  = (const float*)d_in[10];
    float* out = (float*)d_out;

    const int* src = ei;
    const int* dst = ei + E_EDGES;

    float *agg, *h1, *h2, *pool;
    cudaGetSymbolAddress((void**)&agg,  g_agg);
    cudaGetSymbolAddress((void**)&h1,   g_h1);
    cudaGetSymbolAddress((void**)&h2,   g_h2);
    cudaGetSymbolAddress((void**)&pool, g_pool);

    const int n4_agg = N_NODES * DIM / 4;          // 800000
    const int zeroBlocks = 2048;

    const int scatterThreads = E_EDGES * 16;
    const int scatterBlocks = (scatterThreads + 255) / 256;   // 62500

    const int gemmBlocks = (N_NODES + 31) / 32;               // 1563

    const int poolThreads = N_NODES * 16;
    const int poolBlocks = (poolThreads + 255) / 256;

    // ---- layer 1 ----
    zero_kernel<<<zeroBlocks, 256>>>((float4*)agg, n4_agg);
    scatter_add_kernel<<<scatterBlocks, 256>>>(x, src, dst, agg);
    sage_gemm_kernel<<<gemmBlocks, 256>>>(agg, x, Wl1, Wr1, b1, h1, N_NODES);

    // ---- layer 2 ----
    zero_kernel<<<zeroBlocks, 256>>>((float4*)agg, n4_agg);
    scatter_add_kernel<<<scatterBlocks, 256>>>(h1, src, dst, agg);
    sage_gemm_kernel<<<gemmBlocks, 256>>>(agg, h1, Wl2, Wr2, b2, h2, N_NODES);

    // ---- pool + head ----
    zero_kernel<<<64, 256>>>((float4*)pool, G_GRAPHS * DIM / 4);
    pool_kernel<<<poolBlocks, 256>>>(h2, bat, pool);
    head_kernel<<<(G_GRAPHS * O_DIM + 255) / 256, 256>>>(pool, Wo, bo, out);
}

// round 2
// speedup vs baseline: 1.2845x; 1.2845x over previous
#include <cuda_runtime.h>
#include <cuda_bf16.h>

#define N_NODES 50000
#define E_EDGES 1000000
#define DIM     64
#define G_GRAPHS 512
#define O_DIM   16

// Scratch (__device__ globals; no allocation allowed)
__device__ float g_agg [N_NODES * DIM];     // 12.8 MB
__device__ float g_h1  [N_NODES * DIM];     // 12.8 MB
__device__ float g_pool[G_GRAPHS * DIM];    // 128 KB
__device__ int   g_counts[N_NODES];
__device__ int   g_rowptr[N_NODES + 1];
__device__ int   g_cursor[N_NODES];
__device__ int   g_esrc  [E_EDGES];         // 4 MB: src node of each edge, sorted by dst

// ---------------------------------------------------------------------------
// zero counts + pool
// ---------------------------------------------------------------------------
__global__ void zero2_kernel(int* __restrict__ counts, float* __restrict__ pool) {
    int i = blockIdx.x * blockDim.x + threadIdx.x;
    if (i < N_NODES) counts[i] = 0;
    if (i < G_GRAPHS * DIM) pool[i] = 0.f;
}

// ---------------------------------------------------------------------------
// histogram of dst
// ---------------------------------------------------------------------------
__global__ void hist_kernel(const int* __restrict__ dst, int* __restrict__ counts) {
    int e = blockIdx.x * blockDim.x + threadIdx.x;
    if (e < E_EDGES) atomicAdd(&counts[__ldg(&dst[e])], 1);
}

// ---------------------------------------------------------------------------
// single-block exclusive scan of counts -> rowptr (+ cursor copy)
// 1024 threads, each owns a 49-element chunk (1024*49 = 50176 >= 50000)
// ---------------------------------------------------------------------------
__global__ __launch_bounds__(1024) void scan_kernel(const int* __restrict__ counts,
                                                    int* __restrict__ rowptr,
                                                    int* __restrict__ cursor) {
    __shared__ int ssum[1024];
    const int CH = 49;
    int t = threadIdx.x;
    int base = t * CH;

    int s = 0;
    #pragma unroll 7
    for (int i = 0; i < CH; i++) {
        int idx = base + i;
        if (idx < N_NODES) s += __ldg(&counts[idx]);
    }
    ssum[t] = s;
    __syncthreads();

    // Hillis-Steele inclusive scan over 1024 partials
    #pragma unroll
    for (int off = 1; off < 1024; off <<= 1) {
        int v = (t >= off) ? ssum[t - off] : 0;
        __syncthreads();
        ssum[t] += v;
        __syncthreads();
    }

    int run = ssum[t] - s;   // exclusive prefix for this chunk
    #pragma unroll 7
    for (int i = 0; i < CH; i++) {
        int idx = base + i;
        if (idx < N_NODES) {
            rowptr[idx] = run;
            cursor[idx] = run;
            run += __ldg(&counts[idx]);
        }
    }
    if (t == 1023) rowptr[N_NODES] = ssum[1023];   // = E_EDGES
}

// ---------------------------------------------------------------------------
// place edges into dst-sorted order
// ---------------------------------------------------------------------------
__global__ void place_kernel(const int* __restrict__ src, const int* __restrict__ dst,
                             int* __restrict__ cursor, int* __restrict__ esrc) {
    int e = blockIdx.x * blockDim.x + threadIdx.x;
    if (e >= E_EDGES) return;
    int d = __ldg(&dst[e]);
    int p = atomicAdd(&cursor[d], 1);
    esrc[p] = __ldg(&src[e]);
}

// ---------------------------------------------------------------------------
// CSR gather aggregation: warp per node, float2 per lane, register accumulate
// ---------------------------------------------------------------------------
__global__ __launch_bounds__(256) void aggregate_kernel(const float* __restrict__ feat,
                                                        const int*   __restrict__ rowptr,
                                                        const int*   __restrict__ esrc,
                                                        float*       __restrict__ agg) {
    int warp = (blockIdx.x * blockDim.x + threadIdx.x) >> 5;
    int lane = threadIdx.x & 31;
    if (warp >= N_NODES) return;
    int beg = __ldg(&rowptr[warp]);
    int end = __ldg(&rowptr[warp + 1]);

    float2 a0 = make_float2(0.f, 0.f);
    float2 a1 = make_float2(0.f, 0.f);
    const float2* f2 = (const float2*)feat;

    int e = beg;
    for (; e + 1 < end; e += 2) {
        int s0 = __ldg(&esrc[e]);
        int s1 = __ldg(&esrc[e + 1]);
        float2 v0 = __ldg(&f2[s0 * 32 + lane]);
        float2 v1 = __ldg(&f2[s1 * 32 + lane]);
        a0.x += v0.x; a0.y += v0.y;
        a1.x += v1.x; a1.y += v1.y;
    }
    if (e < end) {
        int s0 = __ldg(&esrc[e]);
        float2 v0 = __ldg(&f2[s0 * 32 + lane]);
        a0.x += v0.x; a0.y += v0.y;
    }
    a0.x += a1.x; a0.y += a1.y;
    ((float2*)agg)[warp * 32 + lane] = a0;
}

// ---------------------------------------------------------------------------
// fused SAGE GEMM:  out = relu( agg @ Wl + x @ Wr + b )
// 128 rows/block, 256 threads, 4 rows x 8 cols per thread.
// POOL=1: instead of storing rows, red.add them into pool[batch[row]].
// Dynamic smem: sWl[4096] sWr[4096] sA[128*66] sX[128*66]  (= 100,352 B)
// ---------------------------------------------------------------------------
template<int POOL>
__global__ __launch_bounds__(256) void sage_gemm_kernel(
        const float* __restrict__ agg, const float* __restrict__ xin,
        const float* __restrict__ Wl,  const float* __restrict__ Wr,
        const float* __restrict__ b,   float* __restrict__ out,
        const int* __restrict__ batch, float* __restrict__ pool, int n) {
    extern __shared__ float smem[];
    float* sWl = smem;                       // 64*64
    float* sWr = smem + 4096;                // 64*64
    float* sA  = smem + 8192;                // 128*66
    float* sX  = sA + 128 * 66;              // 128*66
    __shared__ float sB[64];

    int tid = threadIdx.x;

    for (int i = tid; i < 1024; i += 256) {
        ((float4*)sWl)[i] = __ldg(&((const float4*)Wl)[i]);
        ((float4*)sWr)[i] = __ldg(&((const float4*)Wr)[i]);
    }
    if (tid < 64) sB[tid] = __ldg(&b[tid]);

    int row0 = blockIdx.x * 128;
    // tile loads: 128 rows x 32 float2 per array
    for (int i = tid; i < 4096; i += 256) {
        int r  = i >> 5;
        int c2 = i & 31;
        int gr = row0 + r;
        float2 va = make_float2(0.f, 0.f), vx = va;
        if (gr < n) {
            va = __ldg(&((const float2*)agg)[gr * 32 + c2]);
            vx = __ldg(&((const float2*)xin)[gr * 32 + c2]);
        }
        *(float2*)&sA[r * 66 + c2 * 2] = va;
        *(float2*)&sX[r * 66 + c2 * 2] = vx;
    }
    __syncthreads();

    int cg = (tid & 7) * 8;
    int rg = tid >> 3;          // 0..31; rows rg, rg+32, rg+64, rg+96

    float acc[4][8];
    #pragma unroll
    for (int jj = 0; jj < 4; jj++)
        #pragma unroll
        for (int j = 0; j < 8; j++) acc[jj][j] = sB[cg + j];

    #pragma unroll
    for (int k = 0; k < 64; k++) {
        float4 wl0 = *(const float4*)&sWl[k * 64 + cg];
        float4 wl1 = *(const float4*)&sWl[k * 64 + cg + 4];
        float4 wr0 = *(const float4*)&sWr[k * 64 + cg];
        float4 wr1 = *(const float4*)&sWr[k * 64 + cg + 4];
        #pragma unroll
        for (int jj = 0; jj < 4; jj++) {
            int r = rg + jj * 32;
            float a = sA[r * 66 + k];
            float h = sX[r * 66 + k];
            acc[jj][0] += a * wl0.x + h * wr0.x;
            acc[jj][1] += a * wl0.y + h * wr0.y;
            acc[jj][2] += a * wl0.z + h * wr0.z;
            acc[jj][3] += a * wl0.w + h * wr0.w;
            acc[jj][4] += a * wl1.x + h * wr1.x;
            acc[jj][5] += a * wl1.y + h * wr1.y;
            acc[jj][6] += a * wl1.z + h * wr1.z;
            acc[jj][7] += a * wl1.w + h * wr1.w;
        }
    }

    #pragma unroll
    for (int jj = 0; jj < 4; jj++) {
        int gr = row0 + rg + jj * 32;
        if (gr >= n) continue;
        float4 o0, o1;
        o0.x = fmaxf(acc[jj][0], 0.f); o0.y = fmaxf(acc[jj][1], 0.f);
        o0.z = fmaxf(acc[jj][2], 0.f); o0.w = fmaxf(acc[jj][3], 0.f);
        o1.x = fmaxf(acc[jj][4], 0.f); o1.y = fmaxf(acc[jj][5], 0.f);
        o1.z = fmaxf(acc[jj][6], 0.f); o1.w = fmaxf(acc[jj][7], 0.f);
        if (POOL) {
            int bg = __ldg(&batch[gr]);
            float* p = &pool[bg * 64 + cg];
            asm volatile("red.global.add.v4.f32 [%0], {%1,%2,%3,%4};"
                         :: "l"(p), "f"(o0.x), "f"(o0.y), "f"(o0.z), "f"(o0.w) : "memory");
            asm volatile("red.global.add.v4.f32 [%0], {%1,%2,%3,%4};"
                         :: "l"(p + 4), "f"(o1.x), "f"(o1.y), "f"(o1.z), "f"(o1.w) : "memory");
        } else {
            float4* op = (float4*)&out[gr * 64 + cg];
            op[0] = o0;
            op[1] = o1;
        }
    }
}

// ---------------------------------------------------------------------------
// head:  out = pool @ Wo + bo     [512,64] @ [64,16] -> [512,16]
// ---------------------------------------------------------------------------
__global__ void head_kernel(const float* __restrict__ pool,
                            const float* __restrict__ Wo,
                            const float* __restrict__ bo,
                            float*       __restrict__ out) {
    __shared__ float sW[64 * 16];
    __shared__ float sb[16];
    int tid = threadIdx.x;
    for (int i = tid; i < 64 * 16; i += 256) sW[i] = __ldg(&Wo[i]);
    if (tid < 16) sb[tid] = __ldg(&bo[tid]);
    __syncthreads();

    int t = blockIdx.x * blockDim.x + tid;
    if (t >= G_GRAPHS * O_DIM) return;
    int row = t >> 4;
    int col = t & 15;
    float acc = sb[col];
    const float* pr = &pool[row * 64];
    #pragma unroll
    for (int k = 0; k < 64; k++) acc += pr[k] * sW[k * 16 + col];
    out[row * O_DIM + col] = acc;
}

// ---------------------------------------------------------------------------
// launch
// ---------------------------------------------------------------------------
extern "C" void kernel_launch(void* const* d_in, const int* in_sizes, int n_in,
                              void* d_out, int out_size) {
    const float* x   = (const float*)d_in[0];
    const int*   ei  = (const int*)  d_in[1];
    const int*   bat = (const int*)  d_in[2];
    const float* Wl1 = (const float*)d_in[3];
    const float* Wr1 = (const float*)d_in[4];
    const float* b1  = (const float*)d_in[5];
    const float* Wl2 = (const float*)d_in[6];
    const float* Wr2 = (const float*)d_in[7];
    const float* b2  = (const float*)d_in[8];
    const float* Wo  = (const float*)d_in[9];
    const float* bo  = (const float*)d_in[10];
    float* out = (float*)d_out;

    const int* src = ei;
    const int* dst = ei + E_EDGES;

    float *agg, *h1, *pool;
    int *counts, *rowptr, *cursor, *esrc;
    cudaGetSymbolAddress((void**)&agg,    g_agg);
    cudaGetSymbolAddress((void**)&h1,     g_h1);
    cudaGetSymbolAddress((void**)&pool,   g_pool);
    cudaGetSymbolAddress((void**)&counts, g_counts);
    cudaGetSymbolAddress((void**)&rowptr, g_rowptr);
    cudaGetSymbolAddress((void**)&cursor, g_cursor);
    cudaGetSymbolAddress((void**)&esrc,   g_esrc);

    static bool attr_done = false;
    const int gemmSmem = (8192 + 2 * 128 * 66) * sizeof(float);   // 100,352 B
    if (!attr_done) {
        cudaFuncSetAttribute(sage_gemm_kernel<0>,
                             cudaFuncAttributeMaxDynamicSharedMemorySize, gemmSmem);
        cudaFuncSetAttribute(sage_gemm_kernel<1>,
                             cudaFuncAttributeMaxDynamicSharedMemorySize, gemmSmem);
        attr_done = true;
    }

    const int eBlocks   = (E_EDGES + 255) / 256;       // 3907
    const int aggBlocks = (N_NODES * 32 + 255) / 256;  // 6250 (warp per node)
    const int gemmBlocks = (N_NODES + 127) / 128;      // 391

    // ---- build CSR (once; reused by both layers) + zero pool ----
    zero2_kernel<<<(N_NODES + 255) / 256, 256>>>(counts, pool);
    hist_kernel<<<eBlocks, 256>>>(dst, counts);
    scan_kernel<<<1, 1024>>>(counts, rowptr, cursor);
    place_kernel<<<eBlocks, 256>>>(src, dst, cursor, esrc);

    // ---- layer 1 ----
    aggregate_kernel<<<aggBlocks, 256>>>(x, rowptr, esrc, agg);
    sage_gemm_kernel<0><<<gemmBlocks, 256, gemmSmem>>>(agg, x, Wl1, Wr1, b1,
                                                       h1, nullptr, nullptr, N_NODES);

    // ---- layer 2 (+ fused global add pool) ----
    aggregate_kernel<<<aggBlocks, 256>>>(h1, rowptr, esrc, agg);
    sage_gemm_kernel<1><<<gemmBlocks, 256, gemmSmem>>>(agg, h1, Wl2, Wr2, b2,
                                                       nullptr, bat, pool, N_NODES);

    // ---- head ----
    head_kernel<<<(G_GRAPHS * O_DIM + 255) / 256, 256>>>(pool, Wo, bo, out);
}